// round 9
// baseline (speedup 1.0000x reference)
#include <cuda_runtime.h>
#include <stdint.h>
#include <math.h>

#define NN 40000
#define MAXE 700000   // E (640k) + self loops (40k) with slack

// ---------------------------------------------------------------------------
// Scratch (device globals)
// ---------------------------------------------------------------------------
__device__ float g_xh1[NN * 256];   // x @ gat1_W
__device__ float g_acc1[NN * 256];  // GAT1 output
__device__ float g_as1[NN * 2];
__device__ float g_ad1[NN * 2];
__device__ float g_xh2[NN * 64];    // gat1out @ gat2_W
__device__ float g_as2[NN];
__device__ float g_ad2[NN];
__device__ float g_xw1[NN * 128];   // x @ gcn1_W
__device__ float g_gcn1[NN * 128];  // GCN1 output
__device__ float g_xw2[NN * 64];
__device__ float g_dinv[NN];
__device__ float g_cat[NN * 128];   // [gcn2*wc | gat2*wt]
__device__ float g_y1[NN * 256];
__device__ float g_y2[NN * 128];
// CSR scratch
__device__ int g_counts[NN];
__device__ int g_rs[NN + 1];
__device__ int g_cursor[NN];
__device__ int g_csr[MAXE];         // src ids grouped by dst

// ---------------------------------------------------------------------------
// CSR build
// ---------------------------------------------------------------------------
__global__ void zero_int_kernel(int* p, int n) {
    int i = blockIdx.x * blockDim.x + threadIdx.x;
    if (i < n) p[i] = 0;
}

__global__ void hist_kernel(const int* __restrict__ dst, int* __restrict__ counts,
                            int E, int Etot) {
    int t = blockIdx.x * blockDim.x + threadIdx.x;
    if (t >= Etot) return;
    int d = (t < E) ? dst[t] : (t - E);
    atomicAdd(&counts[d], 1);
}

// single-block exclusive scan of 40k counts -> rs (and cursor), rs[n] = total
__global__ void scan_kernel(const int* __restrict__ counts, int* __restrict__ rs,
                            int* __restrict__ cursor, int n) {
    __shared__ int sums[1024];
    int t = threadIdx.x;
    int per = (n + 1023) >> 10;
    int beg = t * per;
    int end = min(beg + per, n);
    int s = 0;
    for (int i = beg; i < end; i++) s += counts[i];
    sums[t] = s;
    __syncthreads();
    for (int off = 1; off < 1024; off <<= 1) {
        int v = (t >= off) ? sums[t - off] : 0;
        __syncthreads();
        sums[t] += v;
        __syncthreads();
    }
    int base = (t == 0) ? 0 : sums[t - 1];
    for (int i = beg; i < end; i++) {
        rs[i] = base;
        cursor[i] = base;
        base += counts[i];
    }
    if (beg < n && end == n) rs[n] = base;
}

__global__ void csr_fill_kernel(const int* __restrict__ src, const int* __restrict__ dst,
                                int* __restrict__ cursor, int* __restrict__ csr,
                                int E, int Etot) {
    int t = blockIdx.x * blockDim.x + threadIdx.x;
    if (t >= Etot) return;
    int s = (t < E) ? src[t] : (t - E);
    int d = (t < E) ? dst[t] : (t - E);
    int pos = atomicAdd(&cursor[d], 1);
    csr[pos] = s;
}

__global__ void dinv_kernel(const int* __restrict__ counts, float* __restrict__ dinv, int n) {
    int t = blockIdx.x * blockDim.x + threadIdx.x;
    if (t >= n) return;
    dinv[t] = rsqrtf(fmaxf((float)counts[t], 1.0f));
}

// ---------------------------------------------------------------------------
// GEMM: C[M,Nc] = A[M,K] @ B[K,Nc] (+bias).
// 160 x BN block tile, BK=16, 320 threads, 8 x (BN/16) per thread.
// Double-buffered: cp.async for B tile, register-staged transpose for A tile.
// M % 160 == 0, Nc % BN == 0, K % 16 == 0.
// ---------------------------------------------------------------------------
__device__ __forceinline__ void cp_async16(void* sdst, const void* gsrc) {
    unsigned int sa = (unsigned int)__cvta_generic_to_shared(sdst);
    asm volatile("cp.async.ca.shared.global [%0], [%1], 16;" :: "r"(sa), "l"(gsrc));
}

template <int BN>
__global__ __launch_bounds__(320) void gemm3_kernel(
        const float* __restrict__ A, const float* __restrict__ B,
        const float* __restrict__ bias, float* __restrict__ C,
        int Nc, int K) {
    constexpr int TN = BN / 16;          // 8 or 4 cols per thread
    __shared__ float As[2][16][168];     // [k][m], padded
    __shared__ float Bs[2][16][BN];      // [k][n]
    const int t = threadIdx.x;           // 0..319
    const int row0 = blockIdx.y * 160;
    const int col0 = blockIdx.x * BN;
    const int ty = t >> 4;               // 0..19
    const int tx = t & 15;               // 0..15
    const int tr = ty * 8;
    const int tc = tx * TN;

    // A-tile load assignment: 2 float4 per thread (640 total)
    const int ar0 = t >> 2, ac0 = (t & 3) * 4;             // rows 0..79
    const int ar1 = (t + 320) >> 2, ac1 = ac0;             // rows 80..159

    float acc[8][TN];
#pragma unroll
    for (int i = 0; i < 8; i++)
#pragma unroll
        for (int j = 0; j < TN; j++) acc[i][j] = 0.0f;

    const int nch = K >> 4;
    constexpr int BF4 = 16 * BN / 4;     // float4s in B tile

    // ---- prologue: chunk 0 ----
    float4 ra0 = *(const float4*)&A[(size_t)(row0 + ar0) * K + ac0];
    float4 ra1 = *(const float4*)&A[(size_t)(row0 + ar1) * K + ac1];
    for (int idx = t; idx < BF4; idx += 320) {
        int kr = idx / (BN / 4);
        int c4 = (idx % (BN / 4)) * 4;
        cp_async16(&Bs[0][kr][c4], &B[(size_t)kr * Nc + col0 + c4]);
    }
    asm volatile("cp.async.commit_group;");
    As[0][ac0 + 0][ar0] = ra0.x; As[0][ac0 + 1][ar0] = ra0.y;
    As[0][ac0 + 2][ar0] = ra0.z; As[0][ac0 + 3][ar0] = ra0.w;
    As[0][ac1 + 0][ar1] = ra1.x; As[0][ac1 + 1][ar1] = ra1.y;
    As[0][ac1 + 2][ar1] = ra1.z; As[0][ac1 + 3][ar1] = ra1.w;
    asm volatile("cp.async.wait_group 0;" ::: "memory");
    __syncthreads();

    int cur = 0;
    for (int ch = 0; ch < nch; ch++) {
        const int nxt = cur ^ 1;
        const bool has = (ch + 1 < nch);
        float4 na0, na1;
        if (has) {
            const int k0 = (ch + 1) << 4;
            na0 = *(const float4*)&A[(size_t)(row0 + ar0) * K + k0 + ac0];
            na1 = *(const float4*)&A[(size_t)(row0 + ar1) * K + k0 + ac1];
            for (int idx = t; idx < BF4; idx += 320) {
                int kr = idx / (BN / 4);
                int c4 = (idx % (BN / 4)) * 4;
                cp_async16(&Bs[nxt][kr][c4], &B[(size_t)(k0 + kr) * Nc + col0 + c4]);
            }
            asm volatile("cp.async.commit_group;");
        }
#pragma unroll
        for (int kk = 0; kk < 16; kk++) {
            float a[8];
            *(float4*)&a[0] = *(const float4*)&As[cur][kk][tr];
            *(float4*)&a[4] = *(const float4*)&As[cur][kk][tr + 4];
            float b[TN];
#pragma unroll
            for (int j4 = 0; j4 < TN / 4; j4++)
                *(float4*)&b[j4 * 4] = *(const float4*)&Bs[cur][kk][tc + j4 * 4];
#pragma unroll
            for (int i = 0; i < 8; i++)
#pragma unroll
                for (int j = 0; j < TN; j++)
                    acc[i][j] = fmaf(a[i], b[j], acc[i][j]);
        }
        if (has) {
            As[nxt][ac0 + 0][ar0] = na0.x; As[nxt][ac0 + 1][ar0] = na0.y;
            As[nxt][ac0 + 2][ar0] = na0.z; As[nxt][ac0 + 3][ar0] = na0.w;
            As[nxt][ac1 + 0][ar1] = na1.x; As[nxt][ac1 + 1][ar1] = na1.y;
            As[nxt][ac1 + 2][ar1] = na1.z; As[nxt][ac1 + 3][ar1] = na1.w;
            asm volatile("cp.async.wait_group 0;" ::: "memory");
            __syncthreads();
        }
        cur = nxt;
    }

    // ---- epilogue ----
    float bb[TN];
#pragma unroll
    for (int j = 0; j < TN; j++) bb[j] = bias ? bias[col0 + tc + j] : 0.0f;
#pragma unroll
    for (int i = 0; i < 8; i++) {
        const size_t rbase = (size_t)(row0 + tr + i) * Nc + col0 + tc;
#pragma unroll
        for (int j4 = 0; j4 < TN / 4; j4++) {
            float4 o;
            o.x = acc[i][j4 * 4 + 0] + bb[j4 * 4 + 0];
            o.y = acc[i][j4 * 4 + 1] + bb[j4 * 4 + 1];
            o.z = acc[i][j4 * 4 + 2] + bb[j4 * 4 + 2];
            o.w = acc[i][j4 * 4 + 3] + bb[j4 * 4 + 3];
            *(float4*)&C[rbase + j4 * 4] = o;
        }
    }
}

// ---------------------------------------------------------------------------
// Attention logits: per 'row' of xh (row = node*heads + h)
// ---------------------------------------------------------------------------
__global__ void att_kernel(const float* __restrict__ xh, const float* __restrict__ a_src,
                           const float* __restrict__ a_dst, float* __restrict__ out_s,
                           float* __restrict__ out_d, int rows, int heads, int ch) {
    int w = (blockIdx.x * blockDim.x + threadIdx.x) >> 5;
    int lane = threadIdx.x & 31;
    if (w >= rows) return;
    const float* row = xh + (size_t)w * ch;
    const float* as = a_src + (size_t)(w % heads) * ch;
    const float* ad = a_dst + (size_t)(w % heads) * ch;
    float ss = 0.0f, dd = 0.0f;
    for (int c = lane; c < ch; c += 32) {
        float v = row[c];
        ss += v * as[c];
        dd += v * ad[c];
    }
#pragma unroll
    for (int o = 16; o; o >>= 1) {
        ss += __shfl_down_sync(0xFFFFFFFFu, ss, o);
        dd += __shfl_down_sync(0xFFFFFFFFu, dd, o);
    }
    if (lane == 0) { out_s[w] = ss; out_d[w] = dd; }
}

// ---------------------------------------------------------------------------
// GAT pull: one warp per destination node. Fused softmax + aggregate + finalize.
// ---------------------------------------------------------------------------
__global__ __launch_bounds__(256) void gat_pull_2_128(
        const int* __restrict__ rs, const int* __restrict__ csr,
        const float* __restrict__ as_, const float* __restrict__ ad_,
        const float* __restrict__ xh, const float* __restrict__ bias,
        float* __restrict__ out) {
    int d = (blockIdx.x * blockDim.x + threadIdx.x) >> 5;
    int lane = threadIdx.x & 31;
    if (d >= NN) return;
    int beg = rs[d], end = rs[d + 1];
    float ad0 = ad_[d * 2 + 0], ad1 = ad_[d * 2 + 1];
    // pass 1: max logit per head
    float m0 = -INFINITY, m1 = -INFINITY;
    for (int j = beg + lane; j < end; j += 32) {
        int s = __ldg(&csr[j]);
        float l0 = as_[s * 2 + 0] + ad0; l0 = l0 > 0.f ? l0 : 0.2f * l0;
        float l1 = as_[s * 2 + 1] + ad1; l1 = l1 > 0.f ? l1 : 0.2f * l1;
        m0 = fmaxf(m0, l0); m1 = fmaxf(m1, l1);
    }
#pragma unroll
    for (int o = 16; o; o >>= 1) {
        m0 = fmaxf(m0, __shfl_xor_sync(0xFFFFFFFFu, m0, o));
        m1 = fmaxf(m1, __shfl_xor_sync(0xFFFFFFFFu, m1, o));
    }
    // pass 2: exp-sum + weighted feature sum
    float s0 = 0.f, s1 = 0.f;
    float f0[4] = {0.f, 0.f, 0.f, 0.f};
    float f1[4] = {0.f, 0.f, 0.f, 0.f};
    for (int j = beg; j < end; ++j) {
        int s = __ldg(&csr[j]);
        float l0 = as_[s * 2 + 0] + ad0; l0 = l0 > 0.f ? l0 : 0.2f * l0;
        float l1 = as_[s * 2 + 1] + ad1; l1 = l1 > 0.f ? l1 : 0.2f * l1;
        float a0 = __expf(l0 - m0), a1 = __expf(l1 - m1);
        s0 += a0; s1 += a1;
        const float4* xs = (const float4*)(xh + (size_t)s * 256);
        float4 v0 = __ldg(xs + lane);        // head0
        float4 v1 = __ldg(xs + lane + 32);   // head1
        f0[0] = fmaf(a0, v0.x, f0[0]); f0[1] = fmaf(a0, v0.y, f0[1]);
        f0[2] = fmaf(a0, v0.z, f0[2]); f0[3] = fmaf(a0, v0.w, f0[3]);
        f1[0] = fmaf(a1, v1.x, f1[0]); f1[1] = fmaf(a1, v1.y, f1[1]);
        f1[2] = fmaf(a1, v1.z, f1[2]); f1[3] = fmaf(a1, v1.w, f1[3]);
    }
    float i0 = 1.0f / (s0 + 1e-16f), i1 = 1.0f / (s1 + 1e-16f);
    float4 o0, o1;
    const float4* b0 = (const float4*)bias;
    float4 bb0 = b0[lane], bb1 = b0[lane + 32];
    o0.x = f0[0] * i0 + bb0.x; o0.y = f0[1] * i0 + bb0.y;
    o0.z = f0[2] * i0 + bb0.z; o0.w = f0[3] * i0 + bb0.w;
    o1.x = f1[0] * i1 + bb1.x; o1.y = f1[1] * i1 + bb1.y;
    o1.z = f1[2] * i1 + bb1.z; o1.w = f1[3] * i1 + bb1.w;
    o0.x = o0.x > 0.f ? o0.x : expm1f(o0.x);
    o0.y = o0.y > 0.f ? o0.y : expm1f(o0.y);
    o0.z = o0.z > 0.f ? o0.z : expm1f(o0.z);
    o0.w = o0.w > 0.f ? o0.w : expm1f(o0.w);
    o1.x = o1.x > 0.f ? o1.x : expm1f(o1.x);
    o1.y = o1.y > 0.f ? o1.y : expm1f(o1.y);
    o1.z = o1.z > 0.f ? o1.z : expm1f(o1.z);
    o1.w = o1.w > 0.f ? o1.w : expm1f(o1.w);
    float4* op = (float4*)(out + (size_t)d * 256);
    op[lane] = o0;
    op[lane + 32] = o1;
}

// GAT head=1, ch=64; writes (agg + bias) * scale into out[d*ostride + ooff + c]
__global__ __launch_bounds__(256) void gat_pull_1_64(
        const int* __restrict__ rs, const int* __restrict__ csr,
        const float* __restrict__ as_, const float* __restrict__ ad_,
        const float* __restrict__ xh, const float* __restrict__ bias,
        const float* __restrict__ scale, float* __restrict__ out,
        int ostride, int ooff) {
    int d = (blockIdx.x * blockDim.x + threadIdx.x) >> 5;
    int lane = threadIdx.x & 31;
    if (d >= NN) return;
    int beg = rs[d], end = rs[d + 1];
    float add = ad_[d];
    float m = -INFINITY;
    for (int j = beg + lane; j < end; j += 32) {
        int s = __ldg(&csr[j]);
        float l = as_[s] + add; l = l > 0.f ? l : 0.2f * l;
        m = fmaxf(m, l);
    }
#pragma unroll
    for (int o = 16; o; o >>= 1) m = fmaxf(m, __shfl_xor_sync(0xFFFFFFFFu, m, o));
    float ssum = 0.f, f0 = 0.f, f1 = 0.f;
    for (int j = beg; j < end; ++j) {
        int s = __ldg(&csr[j]);
        float l = as_[s] + add; l = l > 0.f ? l : 0.2f * l;
        float a = __expf(l - m);
        ssum += a;
        const float2* xs = (const float2*)(xh + (size_t)s * 64);
        float2 v = __ldg(xs + lane);
        f0 = fmaf(a, v.x, f0); f1 = fmaf(a, v.y, f1);
    }
    float sc = scale[0];
    float inv = 1.0f / (ssum + 1e-16f);
    float2 o;
    o.x = (f0 * inv + bias[lane * 2 + 0]) * sc;
    o.y = (f1 * inv + bias[lane * 2 + 1]) * sc;
    ((float2*)(out + (size_t)d * ostride + ooff))[lane] = o;
}

// ---------------------------------------------------------------------------
// GCN pull: one warp per destination node, fused bias/relu.
// ---------------------------------------------------------------------------
__global__ __launch_bounds__(256) void gcn_pull_128(
        const int* __restrict__ rs, const int* __restrict__ csr,
        const float* __restrict__ dinv, const float* __restrict__ xw,
        const float* __restrict__ bias, float* __restrict__ out, int relu) {
    int d = (blockIdx.x * blockDim.x + threadIdx.x) >> 5;
    int lane = threadIdx.x & 31;
    if (d >= NN) return;
    int beg = rs[d], end = rs[d + 1];
    float dd = dinv[d];
    float f[4] = {0.f, 0.f, 0.f, 0.f};
    for (int j = beg; j < end; ++j) {
        int s = __ldg(&csr[j]);
        float nrm = __ldg(&dinv[s]) * dd;
        float4 v = __ldg((const float4*)(xw + (size_t)s * 128) + lane);
        f[0] = fmaf(nrm, v.x, f[0]); f[1] = fmaf(nrm, v.y, f[1]);
        f[2] = fmaf(nrm, v.z, f[2]); f[3] = fmaf(nrm, v.w, f[3]);
    }
    float4 bb = ((const float4*)bias)[lane];
    float4 o;
    o.x = f[0] + bb.x; o.y = f[1] + bb.y; o.z = f[2] + bb.z; o.w = f[3] + bb.w;
    if (relu) {
        o.x = fmaxf(o.x, 0.f); o.y = fmaxf(o.y, 0.f);
        o.z = fmaxf(o.z, 0.f); o.w = fmaxf(o.w, 0.f);
    }
    ((float4*)(out + (size_t)d * 128))[lane] = o;
}

// GCN ch=64; writes (agg + bias) * scale into out[d*ostride + ooff + c]
__global__ __launch_bounds__(256) void gcn_pull_64(
        const int* __restrict__ rs, const int* __restrict__ csr,
        const float* __restrict__ dinv, const float* __restrict__ xw,
        const float* __restrict__ bias, const float* __restrict__ scale,
        float* __restrict__ out, int ostride, int ooff) {
    int d = (blockIdx.x * blockDim.x + threadIdx.x) >> 5;
    int lane = threadIdx.x & 31;
    if (d >= NN) return;
    int beg = rs[d], end = rs[d + 1];
    float dd = dinv[d];
    float f0 = 0.f, f1 = 0.f;
    for (int j = beg; j < end; ++j) {
        int s = __ldg(&csr[j]);
        float nrm = __ldg(&dinv[s]) * dd;
        float2 v = __ldg((const float2*)(xw + (size_t)s * 64) + lane);
        f0 = fmaf(nrm, v.x, f0); f1 = fmaf(nrm, v.y, f1);
    }
    float sc = scale[0];
    float2 o;
    o.x = (f0 + bias[lane * 2 + 0]) * sc;
    o.y = (f1 + bias[lane * 2 + 1]) * sc;
    ((float2*)(out + (size_t)d * ostride + ooff))[lane] = o;
}

// ---------------------------------------------------------------------------
static inline int cdiv(int a, int b) { return (a + b - 1) / b; }

extern "C" void kernel_launch(void* const* d_in, const int* in_sizes, int n_in,
                              void* d_out, int out_size) {
    const float* x      = (const float*)d_in[0];
    const int*   src    = (const int*)d_in[1];
    const int    E      = in_sizes[1] / 2;
    const int*   dst    = src + E;
    const float* gat1_W = (const float*)d_in[2];
    const float* att_s1 = (const float*)d_in[3];
    const float* att_d1 = (const float*)d_in[4];
    const float* gat1_b = (const float*)d_in[5];
    const float* gat2_W = (const float*)d_in[6];
    const float* att_s2 = (const float*)d_in[7];
    const float* att_d2 = (const float*)d_in[8];
    const float* gat2_b = (const float*)d_in[9];
    const float* gcn1_W = (const float*)d_in[10];
    const float* gcn1_b = (const float*)d_in[11];
    const float* gcn2_W = (const float*)d_in[12];
    const float* gcn2_b = (const float*)d_in[13];
    const float* lin1_W = (const float*)d_in[14];
    const float* lin1_b = (const float*)d_in[15];
    const float* lin2_W = (const float*)d_in[16];
    const float* lin2_b = (const float*)d_in[17];
    const float* lin3_W = (const float*)d_in[18];
    const float* lin3_b = (const float*)d_in[19];
    const float* wt     = (const float*)d_in[20];
    const float* wc     = (const float*)d_in[21];

    const int Etot = E + NN;

    float *xh1, *acc1, *as1, *ad1, *xh2, *as2, *ad2;
    float *xw1, *gcn1, *xw2, *dinv, *cat, *y1, *y2;
    int *counts, *rsp, *cursor, *csr;
    cudaGetSymbolAddress((void**)&xh1, g_xh1);
    cudaGetSymbolAddress((void**)&acc1, g_acc1);
    cudaGetSymbolAddress((void**)&as1, g_as1);
    cudaGetSymbolAddress((void**)&ad1, g_ad1);
    cudaGetSymbolAddress((void**)&xh2, g_xh2);
    cudaGetSymbolAddress((void**)&as2, g_as2);
    cudaGetSymbolAddress((void**)&ad2, g_ad2);
    cudaGetSymbolAddress((void**)&xw1, g_xw1);
    cudaGetSymbolAddress((void**)&gcn1, g_gcn1);
    cudaGetSymbolAddress((void**)&xw2, g_xw2);
    cudaGetSymbolAddress((void**)&dinv, g_dinv);
    cudaGetSymbolAddress((void**)&cat, g_cat);
    cudaGetSymbolAddress((void**)&y1, g_y1);
    cudaGetSymbolAddress((void**)&y2, g_y2);
    cudaGetSymbolAddress((void**)&counts, g_counts);
    cudaGetSymbolAddress((void**)&rsp, g_rs);
    cudaGetSymbolAddress((void**)&cursor, g_cursor);
    cudaGetSymbolAddress((void**)&csr, g_csr);

    const int TB = 256;

    // ---- CSR build (dst-grouped src list) ----
    zero_int_kernel<<<cdiv(NN, TB), TB>>>(counts, NN);                      // 1
    hist_kernel<<<cdiv(Etot, TB), TB>>>(dst, counts, E, Etot);              // 2
    scan_kernel<<<1, 1024>>>(counts, rsp, cursor, NN);                      // 3
    csr_fill_kernel<<<cdiv(Etot, TB), TB>>>(src, dst, cursor, csr, E, Etot);// 4
    dinv_kernel<<<cdiv(NN, TB), TB>>>(counts, dinv, NN);                    // 5

    // ---- dense projections from x (6th launch = ncu-profiled) ----
    gemm3_kernel<128><<<dim3(2, NN / 160), 320>>>(x, gat1_W, nullptr, xh1, 256, 128);
    gemm3_kernel<128><<<dim3(1, NN / 160), 320>>>(x, gcn1_W, nullptr, xw1, 128, 128);

    // ---- GAT layer 1 (heads=2, ch=128) ----
    att_kernel<<<cdiv(NN * 2 * 32, TB), TB>>>(xh1, att_s1, att_d1, as1, ad1, NN * 2, 2, 128);
    gat_pull_2_128<<<cdiv(NN * 32, TB), TB>>>(rsp, csr, as1, ad1, xh1, gat1_b, acc1);

    // ---- GAT layer 2 (heads=1, ch=64) -> cat[:, 64:128] * wt ----
    gemm3_kernel<64><<<dim3(1, NN / 160), 320>>>(acc1, gat2_W, nullptr, xh2, 64, 256);
    att_kernel<<<cdiv(NN * 32, TB), TB>>>(xh2, att_s2, att_d2, as2, ad2, NN, 1, 64);
    gat_pull_1_64<<<cdiv(NN * 32, TB), TB>>>(rsp, csr, as2, ad2, xh2, gat2_b, wt, cat, 128, 64);

    // ---- GCN layer 1 (relu fused) ----
    gcn_pull_128<<<cdiv(NN * 32, TB), TB>>>(rsp, csr, dinv, xw1, gcn1_b, gcn1, 1);

    // ---- GCN layer 2 -> cat[:, 0:64] * wc ----
    gemm3_kernel<64><<<dim3(1, NN / 160), 320>>>(gcn1, gcn2_W, nullptr, xw2, 64, 128);
    gcn_pull_64<<<cdiv(NN * 32, TB), TB>>>(rsp, csr, dinv, xw2, gcn2_b, wc, cat, 128, 0);

    // ---- MLP head ----
    gemm3_kernel<128><<<dim3(2, NN / 160), 320>>>(cat, lin1_W, lin1_b, y1, 256, 128);
    gemm3_kernel<128><<<dim3(1, NN / 160), 320>>>(y1, lin2_W, lin2_b, y2, 128, 256);
    gemm3_kernel<64><<<dim3(1, NN / 160), 320>>>(y2, lin3_W, lin3_b, (float*)d_out, 64, 128);
}

// round 10
// speedup vs baseline: 1.5459x; 1.5459x over previous
#include <cuda_runtime.h>
#include <stdint.h>
#include <math.h>

#define NN 40000
#define MAXE 700000   // E (640k) + self loops (40k) with slack

// ---------------------------------------------------------------------------
// Scratch (device globals)
// ---------------------------------------------------------------------------
__device__ float g_xh1[NN * 256];   // x @ gat1_W
__device__ float g_acc1[NN * 256];  // GAT1 output
__device__ float g_as1[NN * 2];
__device__ float g_ad1[NN * 2];
__device__ float g_xh2[NN * 64];    // gat1out @ gat2_W
__device__ float g_as2[NN];
__device__ float g_ad2[NN];
__device__ float g_xw1[NN * 128];   // x @ gcn1_W
__device__ float g_gcn1[NN * 128];  // GCN1 output
__device__ float g_xw2[NN * 64];
__device__ float g_dinv[NN];
__device__ float g_cat[NN * 128];   // [gcn2*wc | gat2*wt]
__device__ float g_y1[NN * 256];
__device__ float g_y2[NN * 128];
// CSR scratch
__device__ int g_counts[NN];
__device__ int g_rs[NN + 1];
__device__ int g_cursor[NN];
__device__ int g_csr[MAXE];         // src ids grouped by dst

// ---------------------------------------------------------------------------
// CSR build
// ---------------------------------------------------------------------------
__global__ void zero_int_kernel(int* p, int n) {
    int i = blockIdx.x * blockDim.x + threadIdx.x;
    if (i < n) p[i] = 0;
}

__global__ void hist_kernel(const int* __restrict__ dst, int* __restrict__ counts,
                            int E, int Etot) {
    int t = blockIdx.x * blockDim.x + threadIdx.x;
    if (t >= Etot) return;
    int d = (t < E) ? dst[t] : (t - E);
    atomicAdd(&counts[d], 1);
}

// single-block exclusive scan of 40k counts -> rs (and cursor), rs[n] = total
__global__ void scan_kernel(const int* __restrict__ counts, int* __restrict__ rs,
                            int* __restrict__ cursor, int n) {
    __shared__ int sums[1024];
    int t = threadIdx.x;
    int per = (n + 1023) >> 10;
    int beg = t * per;
    int end = min(beg + per, n);
    int s = 0;
    for (int i = beg; i < end; i++) s += counts[i];
    sums[t] = s;
    __syncthreads();
    for (int off = 1; off < 1024; off <<= 1) {
        int v = (t >= off) ? sums[t - off] : 0;
        __syncthreads();
        sums[t] += v;
        __syncthreads();
    }
    int base = (t == 0) ? 0 : sums[t - 1];
    for (int i = beg; i < end; i++) {
        rs[i] = base;
        cursor[i] = base;
        base += counts[i];
    }
    if (beg < n && end == n) rs[n] = base;
}

__global__ void csr_fill_kernel(const int* __restrict__ src, const int* __restrict__ dst,
                                int* __restrict__ cursor, int* __restrict__ csr,
                                int E, int Etot) {
    int t = blockIdx.x * blockDim.x + threadIdx.x;
    if (t >= Etot) return;
    int s = (t < E) ? src[t] : (t - E);
    int d = (t < E) ? dst[t] : (t - E);
    int pos = atomicAdd(&cursor[d], 1);
    csr[pos] = s;
}

__global__ void dinv_kernel(const int* __restrict__ counts, float* __restrict__ dinv, int n) {
    int t = blockIdx.x * blockDim.x + threadIdx.x;
    if (t >= n) return;
    dinv[t] = rsqrtf(fmaxf((float)counts[t], 1.0f));
}

// ---------------------------------------------------------------------------
// TF32 tensor-core GEMM: C[M,Nc] = A[M,K] @ B[K,Nc] (+bias)
// Block tile 64 x BN, BK=32, 256 threads = 8 warps (2 m-warps x 4 n-warps),
// warp tile 32 x (BN/4). mma.sync.m16n8k8.tf32, fp32 accumulate.
// M % 64 == 0, Nc % BN == 0, K % 32 == 0.
// ---------------------------------------------------------------------------
__device__ __forceinline__ uint32_t f2tf(float x) {
    uint32_t r;
    asm("cvt.rna.tf32.f32 %0, %1;" : "=r"(r) : "f"(x));
    return r;
}

__device__ __forceinline__ void mma_tf32(float* c, const uint32_t* a, const uint32_t* b) {
    asm volatile(
        "mma.sync.aligned.m16n8k8.row.col.f32.tf32.tf32.f32 "
        "{%0,%1,%2,%3}, {%4,%5,%6,%7}, {%8,%9}, {%0,%1,%2,%3};"
        : "+f"(c[0]), "+f"(c[1]), "+f"(c[2]), "+f"(c[3])
        : "r"(a[0]), "r"(a[1]), "r"(a[2]), "r"(a[3]), "r"(b[0]), "r"(b[1]));
}

template <int BN>
__global__ __launch_bounds__(256) void gemm_tf32_kernel(
        const float* __restrict__ A, const float* __restrict__ B,
        const float* __restrict__ bias, float* __restrict__ C,
        int Nc, int K) {
    constexpr int WN = BN / 4;        // cols per n-warp (32 or 16)
    constexpr int NT = WN / 8;        // n-tiles per warp (4 or 2)
    constexpr int NB4 = BN / 4;       // float4s per B k-row
    constexpr int BLD = (BN == 128) ? 4 : 2;   // B float4 loads per thread
    __shared__ float As[64][36];      // [m][k], stride 36 -> conflict-free frags
    __shared__ float Bs[32][BN + 8];  // [k][n], stride BN+8 -> conflict-free frags

    const int t = threadIdx.x;
    const int lane = t & 31;
    const int w = t >> 5;             // 0..7
    const int wm = w & 1;             // 0..1 (m-warp)
    const int wn = w >> 1;            // 0..3 (n-warp)
    const int row0 = blockIdx.y * 64;
    const int col0 = blockIdx.x * BN;

    // staging assignments
    const int ar0 = t >> 3, acc4_0 = (t & 7) * 4;            // A float4 #t
    const int ar1 = (t + 256) >> 3, acc4_1 = acc4_0;         // A float4 #t+256

    float acc[2][NT][4];
#pragma unroll
    for (int mi = 0; mi < 2; mi++)
#pragma unroll
        for (int ni = 0; ni < NT; ni++)
#pragma unroll
            for (int q = 0; q < 4; q++) acc[mi][ni][q] = 0.0f;

    const int nch = K >> 5;

    float4 pa0, pa1, pb[BLD];
    // prologue loads (chunk 0)
    pa0 = *(const float4*)&A[(size_t)(row0 + ar0) * K + acc4_0];
    pa1 = *(const float4*)&A[(size_t)(row0 + ar1) * K + acc4_1];
#pragma unroll
    for (int i = 0; i < BLD; i++) {
        int id = t + i * 256;
        int kr = id / NB4, c4 = (id % NB4) * 4;
        pb[i] = *(const float4*)&B[(size_t)kr * Nc + col0 + c4];
    }

    for (int ch = 0; ch < nch; ch++) {
        // ---- store staged chunk into smem (tf32-rounded) ----
        As[ar0][acc4_0 + 0] = __uint_as_float(f2tf(pa0.x));
        As[ar0][acc4_0 + 1] = __uint_as_float(f2tf(pa0.y));
        As[ar0][acc4_0 + 2] = __uint_as_float(f2tf(pa0.z));
        As[ar0][acc4_0 + 3] = __uint_as_float(f2tf(pa0.w));
        As[ar1][acc4_1 + 0] = __uint_as_float(f2tf(pa1.x));
        As[ar1][acc4_1 + 1] = __uint_as_float(f2tf(pa1.y));
        As[ar1][acc4_1 + 2] = __uint_as_float(f2tf(pa1.z));
        As[ar1][acc4_1 + 3] = __uint_as_float(f2tf(pa1.w));
#pragma unroll
        for (int i = 0; i < BLD; i++) {
            int id = t + i * 256;
            int kr = id / NB4, c4 = (id % NB4) * 4;
            Bs[kr][c4 + 0] = __uint_as_float(f2tf(pb[i].x));
            Bs[kr][c4 + 1] = __uint_as_float(f2tf(pb[i].y));
            Bs[kr][c4 + 2] = __uint_as_float(f2tf(pb[i].z));
            Bs[kr][c4 + 3] = __uint_as_float(f2tf(pb[i].w));
        }
        __syncthreads();

        // ---- prefetch next chunk into registers ----
        if (ch + 1 < nch) {
            const int k0 = (ch + 1) << 5;
            pa0 = *(const float4*)&A[(size_t)(row0 + ar0) * K + k0 + acc4_0];
            pa1 = *(const float4*)&A[(size_t)(row0 + ar1) * K + k0 + acc4_1];
#pragma unroll
            for (int i = 0; i < BLD; i++) {
                int id = t + i * 256;
                int kr = id / NB4, c4 = (id % NB4) * 4;
                pb[i] = *(const float4*)&B[(size_t)(k0 + kr) * Nc + col0 + c4];
            }
        }

        // ---- compute: 4 k8-steps ----
#pragma unroll
        for (int k8 = 0; k8 < 4; k8++) {
            const int kb = k8 * 8;
            uint32_t af[2][4];
#pragma unroll
            for (int mi = 0; mi < 2; mi++) {
                const int rb = wm * 32 + mi * 16 + (lane >> 2);
                const int cb = kb + (lane & 3);
                af[mi][0] = __float_as_uint(As[rb][cb]);
                af[mi][1] = __float_as_uint(As[rb + 8][cb]);
                af[mi][2] = __float_as_uint(As[rb][cb + 4]);
                af[mi][3] = __float_as_uint(As[rb + 8][cb + 4]);
            }
            uint32_t bf[NT][2];
#pragma unroll
            for (int ni = 0; ni < NT; ni++) {
                const int nb = wn * WN + ni * 8 + (lane >> 2);
                const int kk = kb + (lane & 3);
                bf[ni][0] = __float_as_uint(Bs[kk][nb]);
                bf[ni][1] = __float_as_uint(Bs[kk + 4][nb]);
            }
#pragma unroll
            for (int mi = 0; mi < 2; mi++)
#pragma unroll
                for (int ni = 0; ni < NT; ni++)
                    mma_tf32(acc[mi][ni], af[mi], bf[ni]);
        }
        __syncthreads();
    }

    // ---- epilogue ----
#pragma unroll
    for (int mi = 0; mi < 2; mi++) {
        const int rowa = row0 + wm * 32 + mi * 16 + (lane >> 2);
#pragma unroll
        for (int ni = 0; ni < NT; ni++) {
            const int col = col0 + wn * WN + ni * 8 + (lane & 3) * 2;
            float b0 = bias ? bias[col] : 0.0f;
            float b1 = bias ? bias[col + 1] : 0.0f;
            float2 s0, s1;
            s0.x = acc[mi][ni][0] + b0; s0.y = acc[mi][ni][1] + b1;
            s1.x = acc[mi][ni][2] + b0; s1.y = acc[mi][ni][3] + b1;
            *(float2*)&C[(size_t)rowa * Nc + col] = s0;
            *(float2*)&C[(size_t)(rowa + 8) * Nc + col] = s1;
        }
    }
}

// ---------------------------------------------------------------------------
// Attention logits: per 'row' of xh (row = node*heads + h)
// ---------------------------------------------------------------------------
__global__ void att_kernel(const float* __restrict__ xh, const float* __restrict__ a_src,
                           const float* __restrict__ a_dst, float* __restrict__ out_s,
                           float* __restrict__ out_d, int rows, int heads, int ch) {
    int w = (blockIdx.x * blockDim.x + threadIdx.x) >> 5;
    int lane = threadIdx.x & 31;
    if (w >= rows) return;
    const float* row = xh + (size_t)w * ch;
    const float* as = a_src + (size_t)(w % heads) * ch;
    const float* ad = a_dst + (size_t)(w % heads) * ch;
    float ss = 0.0f, dd = 0.0f;
    for (int c = lane; c < ch; c += 32) {
        float v = row[c];
        ss += v * as[c];
        dd += v * ad[c];
    }
#pragma unroll
    for (int o = 16; o; o >>= 1) {
        ss += __shfl_down_sync(0xFFFFFFFFu, ss, o);
        dd += __shfl_down_sync(0xFFFFFFFFu, dd, o);
    }
    if (lane == 0) { out_s[w] = ss; out_d[w] = dd; }
}

// ---------------------------------------------------------------------------
// GAT pull: one warp per destination node. Fused softmax + aggregate + finalize.
// ---------------------------------------------------------------------------
__global__ __launch_bounds__(256) void gat_pull_2_128(
        const int* __restrict__ rs, const int* __restrict__ csr,
        const float* __restrict__ as_, const float* __restrict__ ad_,
        const float* __restrict__ xh, const float* __restrict__ bias,
        float* __restrict__ out) {
    int d = (blockIdx.x * blockDim.x + threadIdx.x) >> 5;
    int lane = threadIdx.x & 31;
    if (d >= NN) return;
    int beg = rs[d], end = rs[d + 1];
    float ad0 = ad_[d * 2 + 0], ad1 = ad_[d * 2 + 1];
    float m0 = -INFINITY, m1 = -INFINITY;
    for (int j = beg + lane; j < end; j += 32) {
        int s = __ldg(&csr[j]);
        float l0 = as_[s * 2 + 0] + ad0; l0 = l0 > 0.f ? l0 : 0.2f * l0;
        float l1 = as_[s * 2 + 1] + ad1; l1 = l1 > 0.f ? l1 : 0.2f * l1;
        m0 = fmaxf(m0, l0); m1 = fmaxf(m1, l1);
    }
#pragma unroll
    for (int o = 16; o; o >>= 1) {
        m0 = fmaxf(m0, __shfl_xor_sync(0xFFFFFFFFu, m0, o));
        m1 = fmaxf(m1, __shfl_xor_sync(0xFFFFFFFFu, m1, o));
    }
    float s0 = 0.f, s1 = 0.f;
    float f0[4] = {0.f, 0.f, 0.f, 0.f};
    float f1[4] = {0.f, 0.f, 0.f, 0.f};
    for (int j = beg; j < end; ++j) {
        int s = __ldg(&csr[j]);
        float l0 = as_[s * 2 + 0] + ad0; l0 = l0 > 0.f ? l0 : 0.2f * l0;
        float l1 = as_[s * 2 + 1] + ad1; l1 = l1 > 0.f ? l1 : 0.2f * l1;
        float a0 = __expf(l0 - m0), a1 = __expf(l1 - m1);
        s0 += a0; s1 += a1;
        const float4* xs = (const float4*)(xh + (size_t)s * 256);
        float4 v0 = __ldg(xs + lane);
        float4 v1 = __ldg(xs + lane + 32);
        f0[0] = fmaf(a0, v0.x, f0[0]); f0[1] = fmaf(a0, v0.y, f0[1]);
        f0[2] = fmaf(a0, v0.z, f0[2]); f0[3] = fmaf(a0, v0.w, f0[3]);
        f1[0] = fmaf(a1, v1.x, f1[0]); f1[1] = fmaf(a1, v1.y, f1[1]);
        f1[2] = fmaf(a1, v1.z, f1[2]); f1[3] = fmaf(a1, v1.w, f1[3]);
    }
    float i0 = 1.0f / (s0 + 1e-16f), i1 = 1.0f / (s1 + 1e-16f);
    float4 o0, o1;
    const float4* b0 = (const float4*)bias;
    float4 bb0 = b0[lane], bb1 = b0[lane + 32];
    o0.x = f0[0] * i0 + bb0.x; o0.y = f0[1] * i0 + bb0.y;
    o0.z = f0[2] * i0 + bb0.z; o0.w = f0[3] * i0 + bb0.w;
    o1.x = f1[0] * i1 + bb1.x; o1.y = f1[1] * i1 + bb1.y;
    o1.z = f1[2] * i1 + bb1.z; o1.w = f1[3] * i1 + bb1.w;
    o0.x = o0.x > 0.f ? o0.x : expm1f(o0.x);
    o0.y = o0.y > 0.f ? o0.y : expm1f(o0.y);
    o0.z = o0.z > 0.f ? o0.z : expm1f(o0.z);
    o0.w = o0.w > 0.f ? o0.w : expm1f(o0.w);
    o1.x = o1.x > 0.f ? o1.x : expm1f(o1.x);
    o1.y = o1.y > 0.f ? o1.y : expm1f(o1.y);
    o1.z = o1.z > 0.f ? o1.z : expm1f(o1.z);
    o1.w = o1.w > 0.f ? o1.w : expm1f(o1.w);
    float4* op = (float4*)(out + (size_t)d * 256);
    op[lane] = o0;
    op[lane + 32] = o1;
}

// GAT head=1, ch=64; writes (agg + bias) * scale into out[d*ostride + ooff + c]
__global__ __launch_bounds__(256) void gat_pull_1_64(
        const int* __restrict__ rs, const int* __restrict__ csr,
        const float* __restrict__ as_, const float* __restrict__ ad_,
        const float* __restrict__ xh, const float* __restrict__ bias,
        const float* __restrict__ scale, float* __restrict__ out,
        int ostride, int ooff) {
    int d = (blockIdx.x * blockDim.x + threadIdx.x) >> 5;
    int lane = threadIdx.x & 31;
    if (d >= NN) return;
    int beg = rs[d], end = rs[d + 1];
    float add = ad_[d];
    float m = -INFINITY;
    for (int j = beg + lane; j < end; j += 32) {
        int s = __ldg(&csr[j]);
        float l = as_[s] + add; l = l > 0.f ? l : 0.2f * l;
        m = fmaxf(m, l);
    }
#pragma unroll
    for (int o = 16; o; o >>= 1) m = fmaxf(m, __shfl_xor_sync(0xFFFFFFFFu, m, o));
    float ssum = 0.f, f0 = 0.f, f1 = 0.f;
    for (int j = beg; j < end; ++j) {
        int s = __ldg(&csr[j]);
        float l = as_[s] + add; l = l > 0.f ? l : 0.2f * l;
        float a = __expf(l - m);
        ssum += a;
        const float2* xs = (const float2*)(xh + (size_t)s * 64);
        float2 v = __ldg(xs + lane);
        f0 = fmaf(a, v.x, f0); f1 = fmaf(a, v.y, f1);
    }
    float sc = scale[0];
    float inv = 1.0f / (ssum + 1e-16f);
    float2 o;
    o.x = (f0 * inv + bias[lane * 2 + 0]) * sc;
    o.y = (f1 * inv + bias[lane * 2 + 1]) * sc;
    ((float2*)(out + (size_t)d * ostride + ooff))[lane] = o;
}

// ---------------------------------------------------------------------------
// GCN pull: one warp per destination node, fused bias/relu.
// ---------------------------------------------------------------------------
__global__ __launch_bounds__(256) void gcn_pull_128(
        const int* __restrict__ rs, const int* __restrict__ csr,
        const float* __restrict__ dinv, const float* __restrict__ xw,
        const float* __restrict__ bias, float* __restrict__ out, int relu) {
    int d = (blockIdx.x * blockDim.x + threadIdx.x) >> 5;
    int lane = threadIdx.x & 31;
    if (d >= NN) return;
    int beg = rs[d], end = rs[d + 1];
    float dd = dinv[d];
    float f[4] = {0.f, 0.f, 0.f, 0.f};
    for (int j = beg; j < end; ++j) {
        int s = __ldg(&csr[j]);
        float nrm = __ldg(&dinv[s]) * dd;
        float4 v = __ldg((const float4*)(xw + (size_t)s * 128) + lane);
        f[0] = fmaf(nrm, v.x, f[0]); f[1] = fmaf(nrm, v.y, f[1]);
        f[2] = fmaf(nrm, v.z, f[2]); f[3] = fmaf(nrm, v.w, f[3]);
    }
    float4 bb = ((const float4*)bias)[lane];
    float4 o;
    o.x = f[0] + bb.x; o.y = f[1] + bb.y; o.z = f[2] + bb.z; o.w = f[3] + bb.w;
    if (relu) {
        o.x = fmaxf(o.x, 0.f); o.y = fmaxf(o.y, 0.f);
        o.z = fmaxf(o.z, 0.f); o.w = fmaxf(o.w, 0.f);
    }
    ((float4*)(out + (size_t)d * 128))[lane] = o;
}

// GCN ch=64; writes (agg + bias) * scale into out[d*ostride + ooff + c]
__global__ __launch_bounds__(256) void gcn_pull_64(
        const int* __restrict__ rs, const int* __restrict__ csr,
        const float* __restrict__ dinv, const float* __restrict__ xw,
        const float* __restrict__ bias, const float* __restrict__ scale,
        float* __restrict__ out, int ostride, int ooff) {
    int d = (blockIdx.x * blockDim.x + threadIdx.x) >> 5;
    int lane = threadIdx.x & 31;
    if (d >= NN) return;
    int beg = rs[d], end = rs[d + 1];
    float dd = dinv[d];
    float f0 = 0.f, f1 = 0.f;
    for (int j = beg; j < end; ++j) {
        int s = __ldg(&csr[j]);
        float nrm = __ldg(&dinv[s]) * dd;
        float2 v = __ldg((const float2*)(xw + (size_t)s * 64) + lane);
        f0 = fmaf(nrm, v.x, f0); f1 = fmaf(nrm, v.y, f1);
    }
    float sc = scale[0];
    float2 o;
    o.x = (f0 + bias[lane * 2 + 0]) * sc;
    o.y = (f1 + bias[lane * 2 + 1]) * sc;
    ((float2*)(out + (size_t)d * ostride + ooff))[lane] = o;
}

// ---------------------------------------------------------------------------
static inline int cdiv(int a, int b) { return (a + b - 1) / b; }

extern "C" void kernel_launch(void* const* d_in, const int* in_sizes, int n_in,
                              void* d_out, int out_size) {
    const float* x      = (const float*)d_in[0];
    const int*   src    = (const int*)d_in[1];
    const int    E      = in_sizes[1] / 2;
    const int*   dst    = src + E;
    const float* gat1_W = (const float*)d_in[2];
    const float* att_s1 = (const float*)d_in[3];
    const float* att_d1 = (const float*)d_in[4];
    const float* gat1_b = (const float*)d_in[5];
    const float* gat2_W = (const float*)d_in[6];
    const float* att_s2 = (const float*)d_in[7];
    const float* att_d2 = (const float*)d_in[8];
    const float* gat2_b = (const float*)d_in[9];
    const float* gcn1_W = (const float*)d_in[10];
    const float* gcn1_b = (const float*)d_in[11];
    const float* gcn2_W = (const float*)d_in[12];
    const float* gcn2_b = (const float*)d_in[13];
    const float* lin1_W = (const float*)d_in[14];
    const float* lin1_b = (const float*)d_in[15];
    const float* lin2_W = (const float*)d_in[16];
    const float* lin2_b = (const float*)d_in[17];
    const float* lin3_W = (const float*)d_in[18];
    const float* lin3_b = (const float*)d_in[19];
    const float* wt     = (const float*)d_in[20];
    const float* wc     = (const float*)d_in[21];

    const int Etot = E + NN;

    float *xh1, *acc1, *as1, *ad1, *xh2, *as2, *ad2;
    float *xw1, *gcn1, *xw2, *dinv, *cat, *y1, *y2;
    int *counts, *rsp, *cursor, *csr;
    cudaGetSymbolAddress((void**)&xh1, g_xh1);
    cudaGetSymbolAddress((void**)&acc1, g_acc1);
    cudaGetSymbolAddress((void**)&as1, g_as1);
    cudaGetSymbolAddress((void**)&ad1, g_ad1);
    cudaGetSymbolAddress((void**)&xh2, g_xh2);
    cudaGetSymbolAddress((void**)&as2, g_as2);
    cudaGetSymbolAddress((void**)&ad2, g_ad2);
    cudaGetSymbolAddress((void**)&xw1, g_xw1);
    cudaGetSymbolAddress((void**)&gcn1, g_gcn1);
    cudaGetSymbolAddress((void**)&xw2, g_xw2);
    cudaGetSymbolAddress((void**)&dinv, g_dinv);
    cudaGetSymbolAddress((void**)&cat, g_cat);
    cudaGetSymbolAddress((void**)&y1, g_y1);
    cudaGetSymbolAddress((void**)&y2, g_y2);
    cudaGetSymbolAddress((void**)&counts, g_counts);
    cudaGetSymbolAddress((void**)&rsp, g_rs);
    cudaGetSymbolAddress((void**)&cursor, g_cursor);
    cudaGetSymbolAddress((void**)&csr, g_csr);

    const int TB = 256;
    const int GY = NN / 64;   // 625

    // ---- CSR build (dst-grouped src list) ----
    zero_int_kernel<<<cdiv(NN, TB), TB>>>(counts, NN);                      // 1
    hist_kernel<<<cdiv(Etot, TB), TB>>>(dst, counts, E, Etot);              // 2
    scan_kernel<<<1, 1024>>>(counts, rsp, cursor, NN);                      // 3
    csr_fill_kernel<<<cdiv(Etot, TB), TB>>>(src, dst, cursor, csr, E, Etot);// 4
    dinv_kernel<<<cdiv(NN, TB), TB>>>(counts, dinv, NN);                    // 5

    // ---- dense projections from x (6th launch = ncu-profiled) ----
    gemm_tf32_kernel<128><<<dim3(2, GY), 256>>>(x, gat1_W, nullptr, xh1, 256, 128);
    gemm_tf32_kernel<128><<<dim3(1, GY), 256>>>(x, gcn1_W, nullptr, xw1, 128, 128);

    // ---- GAT layer 1 (heads=2, ch=128) ----
    att_kernel<<<cdiv(NN * 2 * 32, TB), TB>>>(xh1, att_s1, att_d1, as1, ad1, NN * 2, 2, 128);
    gat_pull_2_128<<<cdiv(NN * 32, TB), TB>>>(rsp, csr, as1, ad1, xh1, gat1_b, acc1);

    // ---- GAT layer 2 (heads=1, ch=64) -> cat[:, 64:128] * wt ----
    gemm_tf32_kernel<64><<<dim3(1, GY), 256>>>(acc1, gat2_W, nullptr, xh2, 64, 256);
    att_kernel<<<cdiv(NN * 32, TB), TB>>>(xh2, att_s2, att_d2, as2, ad2, NN, 1, 64);
    gat_pull_1_64<<<cdiv(NN * 32, TB), TB>>>(rsp, csr, as2, ad2, xh2, gat2_b, wt, cat, 128, 64);

    // ---- GCN layer 1 (relu fused) ----
    gcn_pull_128<<<cdiv(NN * 32, TB), TB>>>(rsp, csr, dinv, xw1, gcn1_b, gcn1, 1);

    // ---- GCN layer 2 -> cat[:, 0:64] * wc ----
    gemm_tf32_kernel<64><<<dim3(1, GY), 256>>>(gcn1, gcn2_W, nullptr, xw2, 64, 128);
    gcn_pull_64<<<cdiv(NN * 32, TB), TB>>>(rsp, csr, dinv, xw2, gcn2_b, wc, cat, 128, 0);

    // ---- MLP head ----
    gemm_tf32_kernel<128><<<dim3(2, GY), 256>>>(cat, lin1_W, lin1_b, y1, 256, 128);
    gemm_tf32_kernel<128><<<dim3(1, GY), 256>>>(y1, lin2_W, lin2_b, y2, 128, 256);
    gemm_tf32_kernel<64><<<dim3(1, GY), 256>>>(y2, lin3_W, lin3_b, (float*)d_out, 64, 128);
}